// round 3
// baseline (speedup 1.0000x reference)
#include <cuda_runtime.h>

#define N_NODES 50000
#define N_EDGES 800000
#define ET      (N_EDGES + N_NODES)   // 850000 edges incl self loops
#define HEADS   4
#define F12     128                    // 4*32
#define F3      188                    // 4*47
#define NCLS    47
#define NEG_SLOPE 0.2f

// ---------------- scratch (device globals, no allocation) ----------------
__device__ float    g_h[N_NODES * F3];        // linear output of current layer
__device__ float    g_buf[N_NODES * F12];     // activations between layers
__device__ float    g_agg[N_NODES * F3];      // aggregation accumulator
__device__ float    g_asrc[N_NODES * HEADS];
__device__ float    g_adst[N_NODES * HEADS];
__device__ float    g_alpha[(size_t)ET * HEADS];
__device__ unsigned g_max[N_NODES * HEADS];
__device__ float    g_den[N_NODES * HEADS];

// ---------------- float <-> orderable-uint for atomicMax ----------------
__device__ __forceinline__ unsigned f2u(float f) {
    unsigned u = __float_as_uint(f);
    return (u & 0x80000000u) ? ~u : (u | 0x80000000u);
}
__device__ __forceinline__ float u2f(unsigned u) {
    return (u & 0x80000000u) ? __uint_as_float(u ^ 0x80000000u) : __uint_as_float(~u);
}

// ---------------- zero accumulators ----------------
__global__ void zero_kernel() {
    int i = blockIdx.x * blockDim.x + threadIdx.x;
    int stride = gridDim.x * blockDim.x;
    for (int k = i; k < N_NODES * F3; k += stride) g_agg[k] = 0.f;
    for (int k = i; k < N_NODES * HEADS; k += stride) { g_den[k] = 0.f; g_max[k] = 0u; }
}

// ---------------- GEMM + attention coefficients ----------------
// one block per node; thread f computes output feature f, then reduces
// h*att_src / h*att_dst per head via shared atomics.
template <int FIN, int FOUT, int C>
__global__ void gemm_attn_kernel(const float* __restrict__ x,
                                 const float* __restrict__ W,
                                 const float* __restrict__ as,
                                 const float* __restrict__ ad) {
    __shared__ float xs[FIN];
    __shared__ float s_s[HEADS], s_d[HEADS];
    int n = blockIdx.x;
    int f = threadIdx.x;
    for (int k = f; k < FIN; k += blockDim.x) xs[k] = x[n * FIN + k];
    if (f < HEADS) { s_s[f] = 0.f; s_d[f] = 0.f; }
    __syncthreads();
    if (f < FOUT) {
        float acc = 0.f;
#pragma unroll 16
        for (int k = 0; k < FIN; k++) acc = fmaf(xs[k], W[k * FOUT + f], acc);
        g_h[n * FOUT + f] = acc;
        int hh = f / C;
        atomicAdd(&s_s[hh], acc * as[f]);
        atomicAdd(&s_d[hh], acc * ad[f]);
    }
    __syncthreads();
    if (f < HEADS) {
        g_asrc[n * HEADS + f] = s_s[f];
        g_adst[n * HEADS + f] = s_d[f];
    }
}

// ---------------- edge pass 1: alpha + leaky relu + segment max ----------------
__global__ void edge_alpha_kernel(const int* __restrict__ ei) {
    int tid = blockIdx.x * blockDim.x + threadIdx.x;
    if (tid >= ET * HEADS) return;
    int e = tid >> 2;
    int h = tid & 3;
    int src, dst;
    if (e < N_EDGES) { src = ei[e]; dst = ei[N_EDGES + e]; }
    else             { src = dst = e - N_EDGES; }
    float a = g_asrc[src * HEADS + h] + g_adst[dst * HEADS + h];
    a = (a >= 0.f) ? a : NEG_SLOPE * a;
    g_alpha[tid] = a;
    atomicMax(&g_max[dst * HEADS + h], f2u(a));
}

// ---------------- edge pass 2: exp + segment sum ----------------
__global__ void edge_exp_kernel(const int* __restrict__ ei) {
    int tid = blockIdx.x * blockDim.x + threadIdx.x;
    if (tid >= ET * HEADS) return;
    int e = tid >> 2;
    int h = tid & 3;
    int dst;
    if (e < N_EDGES) dst = ei[N_EDGES + e];
    else             dst = e - N_EDGES;
    float m = u2f(g_max[dst * HEADS + h]);
    float w = expf(g_alpha[tid] - m);
    g_alpha[tid] = w;
    atomicAdd(&g_den[dst * HEADS + h], w);
}

// ---------------- edge pass 3: weighted scatter-aggregate (norm fused) ----------------
// one warp per edge. Layer 1/2 (FT=128, C=32): lane l handles float4 at feat 4l.
__global__ void edge_aggregate128_kernel(const int* __restrict__ ei) {
    int gtid = blockIdx.x * blockDim.x + threadIdx.x;
    int e = gtid >> 5;
    int lane = gtid & 31;
    if (e >= ET) return;
    int src, dst;
    if (e < N_EDGES) { src = ei[e]; dst = ei[N_EDGES + e]; }
    else             { src = dst = e - N_EDGES; }
    // normalized weight for head `lane` (lanes 0..3), broadcast below
    float wt = 0.f;
    if (lane < HEADS)
        wt = g_alpha[e * HEADS + lane] / g_den[dst * HEADS + lane];
    // feats [4*lane, 4*lane+4) all belong to head lane>>3
    float w = __shfl_sync(0xFFFFFFFFu, wt, lane >> 3);
    float4 v = *(const float4*)&g_h[src * F12 + 4 * lane];
    float* o = &g_agg[dst * F12 + 4 * lane];
    atomicAdd(o + 0, v.x * w);
    atomicAdd(o + 1, v.y * w);
    atomicAdd(o + 2, v.z * w);
    atomicAdd(o + 3, v.w * w);
}

// Layer 3 (FT=188, C=47): lane handles feats lane, lane+32, ... (6 iters)
__global__ void edge_aggregate188_kernel(const int* __restrict__ ei) {
    int gtid = blockIdx.x * blockDim.x + threadIdx.x;
    int e = gtid >> 5;
    int lane = gtid & 31;
    if (e >= ET) return;
    int src, dst;
    if (e < N_EDGES) { src = ei[e]; dst = ei[N_EDGES + e]; }
    else             { src = dst = e - N_EDGES; }
    float wt = 0.f;
    if (lane < HEADS)
        wt = g_alpha[e * HEADS + lane] / g_den[dst * HEADS + lane];
    float w0 = __shfl_sync(0xFFFFFFFFu, wt, 0);
    float w1 = __shfl_sync(0xFFFFFFFFu, wt, 1);
    float w2 = __shfl_sync(0xFFFFFFFFu, wt, 2);
    float w3 = __shfl_sync(0xFFFFFFFFu, wt, 3);
    const float* hrow = &g_h[src * F3];
    float* orow = &g_agg[dst * F3];
#pragma unroll
    for (int f = lane; f < F3; f += 32) {
        int hh = f / NCLS;
        float w = (hh == 0) ? w0 : (hh == 1) ? w1 : (hh == 2) ? w2 : w3;
        atomicAdd(&orow[f], hrow[f] * w);
    }
}

// ---------------- finalize layers 1/2: bias + relu ----------------
__global__ void finalize12_kernel(const float* __restrict__ b) {
    int tid = blockIdx.x * blockDim.x + threadIdx.x;
    if (tid >= N_NODES * F12) return;
    int f = tid & 127;
    g_buf[tid] = fmaxf(g_agg[tid] + b[f], 0.f);
}

// ---------------- finalize layer 3: head mean + bias + log_softmax ----------------
// one warp per node; lane handles classes lane and lane+32.
__global__ void finalize3_kernel(const float* __restrict__ b3, float* __restrict__ out) {
    int gtid = blockIdx.x * blockDim.x + threadIdx.x;
    int n = gtid >> 5;
    int lane = gtid & 31;
    if (n >= N_NODES) return;
    int c0 = lane, c1 = lane + 32;
    float v0 = -1e30f, v1 = -1e30f;
    const float* row = &g_agg[n * F3];
    if (c0 < NCLS)
        v0 = 0.25f * (row[c0] + row[NCLS + c0] + row[2 * NCLS + c0] + row[3 * NCLS + c0]) + b3[c0];
    if (c1 < NCLS)
        v1 = 0.25f * (row[c1] + row[NCLS + c1] + row[2 * NCLS + c1] + row[3 * NCLS + c1]) + b3[c1];
    float m = fmaxf(v0, v1);
#pragma unroll
    for (int o = 16; o > 0; o >>= 1) m = fmaxf(m, __shfl_xor_sync(0xFFFFFFFFu, m, o));
    float s = 0.f;
    if (c0 < NCLS) s += expf(v0 - m);
    if (c1 < NCLS) s += expf(v1 - m);
#pragma unroll
    for (int o = 16; o > 0; o >>= 1) s += __shfl_xor_sync(0xFFFFFFFFu, s, o);
    float lse = m + logf(s);
    if (c0 < NCLS) out[n * NCLS + c0] = v0 - lse;
    if (c1 < NCLS) out[n * NCLS + c1] = v1 - lse;
}

// ---------------- launch ----------------
static void run_layer12(const float* x, const float* W, const float* as,
                        const float* ad, const float* b, const int* ei) {
    int eb = (ET * HEADS + 255) / 256;
    int wb = (ET * 32 + 255) / 256;
    zero_kernel<<<2048, 256>>>();
    gemm_attn_kernel<F12, F12, 32><<<N_NODES, 128>>>(x, W, as, ad);
    edge_alpha_kernel<<<eb, 256>>>(ei);
    edge_exp_kernel<<<eb, 256>>>(ei);
    edge_aggregate128_kernel<<<wb, 256>>>(ei);
    finalize12_kernel<<<(N_NODES * F12 + 255) / 256, 256>>>(b);
}

extern "C" void kernel_launch(void* const* d_in, const int* in_sizes, int n_in,
                              void* d_out, int out_size) {
    const float* x   = (const float*)d_in[0];
    const int*   ei  = (const int*)d_in[1];   // edge_index is int32 (JAX x64 disabled)
    const float* W1  = (const float*)d_in[2];
    const float* a1s = (const float*)d_in[3];
    const float* a1d = (const float*)d_in[4];
    const float* b1  = (const float*)d_in[5];
    const float* W2  = (const float*)d_in[6];
    const float* a2s = (const float*)d_in[7];
    const float* a2d = (const float*)d_in[8];
    const float* b2  = (const float*)d_in[9];
    const float* W3  = (const float*)d_in[10];
    const float* a3s = (const float*)d_in[11];
    const float* a3d = (const float*)d_in[12];
    const float* b3  = (const float*)d_in[13];
    float* out = (float*)d_out;

    float* g_buf_ptr = nullptr;
    cudaGetSymbolAddress((void**)&g_buf_ptr, g_buf);

    // layer 1: x [N,128] -> g_buf [N,128]
    run_layer12(x, W1, a1s, a1d, b1, ei);
    // layer 2: g_buf -> g_buf
    run_layer12(g_buf_ptr, W2, a2s, a2d, b2, ei);
    // layer 3: g_buf -> out [N,47]
    int eb = (ET * HEADS + 255) / 256;
    int wb = (ET * 32 + 255) / 256;
    zero_kernel<<<2048, 256>>>();
    gemm_attn_kernel<F12, F3, NCLS><<<N_NODES, 192>>>(g_buf_ptr, W3, a3s, a3d);
    edge_alpha_kernel<<<eb, 256>>>(ei);
    edge_exp_kernel<<<eb, 256>>>(ei);
    edge_aggregate188_kernel<<<wb, 256>>>(ei);
    finalize3_kernel<<<(N_NODES * 32 + 255) / 256, 256>>>(b3, out);
}

// round 4
// speedup vs baseline: 1.4935x; 1.4935x over previous
#include <cuda_runtime.h>

#define N_NODES 50000
#define N_EDGES 800000
#define ET      (N_EDGES + N_NODES)   // 850000 edges incl self loops
#define HEADS   4
#define F12     128                    // 4*32
#define F3      188                    // 4*47
#define NCLS    47
#define NEG_SLOPE 0.2f

// ---------------- scratch (device globals, no allocation) ----------------
__device__ float g_h[N_NODES * F3];        // linear output of current layer
__device__ float g_buf[N_NODES * F12];     // activations between layers
__device__ float g_agg[N_NODES * F3];      // layer-3 aggregation (pre-mean)
__device__ float g_asrc[N_NODES * HEADS];
__device__ float g_adst[N_NODES * HEADS];
__device__ float g_w[(size_t)ET * HEADS];  // per-edge raw exp weights (per dst list)
// CSR by destination
__device__ int g_deg[N_NODES];
__device__ int g_rowptr[N_NODES + 1];
__device__ int g_cursor[N_NODES];
__device__ int g_col[ET];                  // src node per slot
__device__ int g_bsum[64];
__device__ int g_boff[64];

// ================= CSR build =================
__global__ void csr_init_kernel() {
    int i = blockIdx.x * blockDim.x + threadIdx.x;
    if (i < N_NODES) { g_deg[i] = 0; g_cursor[i] = 0; }
}

__global__ void csr_hist_kernel(const int* __restrict__ ei) {
    int e = blockIdx.x * blockDim.x + threadIdx.x;
    if (e >= ET) return;
    int dst = (e < N_EDGES) ? ei[N_EDGES + e] : (e - N_EDGES);
    atomicAdd(&g_deg[dst], 1);
}

// block-wise inclusive scan (1024/block), writes exclusive prefix + block sums
__global__ void csr_scan1_kernel() {
    __shared__ int s[1024];
    int t = threadIdx.x;
    int i = blockIdx.x * 1024 + t;
    int v = (i < N_NODES) ? g_deg[i] : 0;
    s[t] = v;
    __syncthreads();
#pragma unroll
    for (int off = 1; off < 1024; off <<= 1) {
        int x = (t >= off) ? s[t - off] : 0;
        __syncthreads();
        s[t] += x;
        __syncthreads();
    }
    if (i <= N_NODES) g_rowptr[i] = s[t] - v;   // exclusive
    if (t == 1023) g_bsum[blockIdx.x] = s[t];
}

__global__ void csr_scan2_kernel(int nblocks) {
    __shared__ int s[64];
    int t = threadIdx.x;
    int v = (t < nblocks) ? g_bsum[t] : 0;
    s[t] = v;
    __syncthreads();
#pragma unroll
    for (int off = 1; off < 64; off <<= 1) {
        int x = (t >= off) ? s[t - off] : 0;
        __syncthreads();
        s[t] += x;
        __syncthreads();
    }
    if (t < nblocks) g_boff[t] = s[t] - v;      // exclusive
}

__global__ void csr_scan3_kernel() {
    int i = blockIdx.x * blockDim.x + threadIdx.x;
    if (i < N_NODES) g_rowptr[i] += g_boff[i >> 10];
    if (i == 0) g_rowptr[N_NODES] = ET;
}

__global__ void csr_scatter_kernel(const int* __restrict__ ei) {
    int e = blockIdx.x * blockDim.x + threadIdx.x;
    if (e >= ET) return;
    int src, dst;
    if (e < N_EDGES) { src = ei[e]; dst = ei[N_EDGES + e]; }
    else             { src = dst = e - N_EDGES; }
    int pos = atomicAdd(&g_cursor[dst], 1);
    g_col[g_rowptr[dst] + pos] = src;
}

// ================= GEMM + attention coefficients =================
// one block per node; thread f computes output feature f, then reduces
// h*att_src / h*att_dst per head via shared atomics.
template <int FIN, int FOUT, int C>
__global__ void gemm_attn_kernel(const float* __restrict__ x,
                                 const float* __restrict__ W,
                                 const float* __restrict__ as,
                                 const float* __restrict__ ad) {
    __shared__ float xs[FIN];
    __shared__ float s_s[HEADS], s_d[HEADS];
    int n = blockIdx.x;
    int f = threadIdx.x;
    for (int k = f; k < FIN; k += blockDim.x) xs[k] = x[n * FIN + k];
    if (f < HEADS) { s_s[f] = 0.f; s_d[f] = 0.f; }
    __syncthreads();
    if (f < FOUT) {
        float acc = 0.f;
#pragma unroll 16
        for (int k = 0; k < FIN; k++) acc = fmaf(xs[k], W[k * FOUT + f], acc);
        g_h[n * FOUT + f] = acc;
        int hh = f / C;
        atomicAdd(&s_s[hh], acc * as[f]);
        atomicAdd(&s_d[hh], acc * ad[f]);
    }
    __syncthreads();
    if (f < HEADS) {
        g_asrc[n * HEADS + f] = s_s[f];
        g_adst[n * HEADS + f] = s_d[f];
    }
}

// ================= fused softmax + gather-aggregate =================
// one warp per destination node. No atomics anywhere.
// pass1: per-(edge,head) alpha -> per-head max (xor-shuffle reduce, head = lane&3
//        preserved by strides 4/8/16)
// pass2: raw exp stored to g_w, per-head denom reduced
// pass3: register accumulation of sum_e h[src]*w_e; normalize once at the end.
__global__ void gat_agg128_kernel(const float* __restrict__ bias) {
    int gtid = blockIdx.x * blockDim.x + threadIdx.x;
    int n = gtid >> 5;
    int lane = gtid & 31;
    if (n >= N_NODES) return;
    int beg = g_rowptr[n];
    int deg = g_rowptr[n + 1] - beg;
    int hme = lane & 3;
    float adst_h = g_adst[n * HEADS + hme];

    // pass 1: max
    float mx = -1e30f;
    for (int p = lane; p < deg * HEADS; p += 32) {
        int src = g_col[beg + (p >> 2)];
        float a = g_asrc[src * HEADS + hme] + adst_h;
        a = (a >= 0.f) ? a : NEG_SLOPE * a;
        mx = fmaxf(mx, a);
    }
    mx = fmaxf(mx, __shfl_xor_sync(0xFFFFFFFFu, mx, 4));
    mx = fmaxf(mx, __shfl_xor_sync(0xFFFFFFFFu, mx, 8));
    mx = fmaxf(mx, __shfl_xor_sync(0xFFFFFFFFu, mx, 16));

    // pass 2: exp + denom, store raw exp
    float den = 0.f;
    for (int p = lane; p < deg * HEADS; p += 32) {
        int src = g_col[beg + (p >> 2)];
        float a = g_asrc[src * HEADS + hme] + adst_h;
        a = (a >= 0.f) ? a : NEG_SLOPE * a;
        float w = __expf(a - mx);
        den += w;
        g_w[(size_t)(beg << 2) + p] = w;
    }
    den += __shfl_xor_sync(0xFFFFFFFFu, den, 4);
    den += __shfl_xor_sync(0xFFFFFFFFu, den, 8);
    den += __shfl_xor_sync(0xFFFFFFFFu, den, 16);
    __syncwarp();

    // pass 3: gather-accumulate. lane owns feats [4*lane,4*lane+4), head = lane>>3
    int hh = lane >> 3;
    float4 acc = make_float4(0.f, 0.f, 0.f, 0.f);
    for (int i = 0; i < deg; i++) {
        int src = g_col[beg + i];
        float4 w4 = *(const float4*)&g_w[(size_t)(beg + i) * 4];  // broadcast
        float w = (hh == 0) ? w4.x : (hh == 1) ? w4.y : (hh == 2) ? w4.z : w4.w;
        float4 v = *(const float4*)&g_h[src * F12 + 4 * lane];
        acc.x = fmaf(v.x, w, acc.x);
        acc.y = fmaf(v.y, w, acc.y);
        acc.z = fmaf(v.z, w, acc.z);
        acc.w = fmaf(v.w, w, acc.w);
    }
    // normalize by this accumulator's head denom (den held by lanes with lane&3==head)
    float idv = 1.f / __shfl_sync(0xFFFFFFFFu, den, hh);
    float4 b4 = *(const float4*)&bias[4 * lane];
    float4 o;
    o.x = fmaxf(fmaf(acc.x, idv, b4.x), 0.f);
    o.y = fmaxf(fmaf(acc.y, idv, b4.y), 0.f);
    o.z = fmaxf(fmaf(acc.z, idv, b4.z), 0.f);
    o.w = fmaxf(fmaf(acc.w, idv, b4.w), 0.f);
    *(float4*)&g_buf[n * F12 + 4 * lane] = o;
}

// layer 3 variant: FT=188, C=47; lane owns feats lane+32k (k<6); writes g_agg raw.
__global__ void gat_agg188_kernel() {
    int gtid = blockIdx.x * blockDim.x + threadIdx.x;
    int n = gtid >> 5;
    int lane = gtid & 31;
    if (n >= N_NODES) return;
    int beg = g_rowptr[n];
    int deg = g_rowptr[n + 1] - beg;
    int hme = lane & 3;
    float adst_h = g_adst[n * HEADS + hme];

    float mx = -1e30f;
    for (int p = lane; p < deg * HEADS; p += 32) {
        int src = g_col[beg + (p >> 2)];
        float a = g_asrc[src * HEADS + hme] + adst_h;
        a = (a >= 0.f) ? a : NEG_SLOPE * a;
        mx = fmaxf(mx, a);
    }
    mx = fmaxf(mx, __shfl_xor_sync(0xFFFFFFFFu, mx, 4));
    mx = fmaxf(mx, __shfl_xor_sync(0xFFFFFFFFu, mx, 8));
    mx = fmaxf(mx, __shfl_xor_sync(0xFFFFFFFFu, mx, 16));

    float den = 0.f;
    for (int p = lane; p < deg * HEADS; p += 32) {
        int src = g_col[beg + (p >> 2)];
        float a = g_asrc[src * HEADS + hme] + adst_h;
        a = (a >= 0.f) ? a : NEG_SLOPE * a;
        float w = __expf(a - mx);
        den += w;
        g_w[(size_t)(beg << 2) + p] = w;
    }
    den += __shfl_xor_sync(0xFFFFFFFFu, den, 4);
    den += __shfl_xor_sync(0xFFFFFFFFu, den, 8);
    den += __shfl_xor_sync(0xFFFFFFFFu, den, 16);
    __syncwarp();

    // head index per accumulator slot (compile-time-ish, lane-dependent)
    int hhk[6];
#pragma unroll
    for (int k = 0; k < 6; k++) hhk[k] = (lane + 32 * k) / NCLS;
    float acc[6] = {0.f, 0.f, 0.f, 0.f, 0.f, 0.f};
    for (int i = 0; i < deg; i++) {
        int src = g_col[beg + i];
        float4 w4 = *(const float4*)&g_w[(size_t)(beg + i) * 4];  // broadcast
        const float* hrow = &g_h[src * F3];
#pragma unroll
        for (int k = 0; k < 6; k++) {
            int f = lane + 32 * k;
            if (f < F3) {
                int hh = hhk[k];
                float w = (hh == 0) ? w4.x : (hh == 1) ? w4.y : (hh == 2) ? w4.z : w4.w;
                acc[k] = fmaf(hrow[f], w, acc[k]);
            }
        }
    }
#pragma unroll
    for (int k = 0; k < 6; k++) {
        int f = lane + 32 * k;
        if (f < F3) {
            float idv = 1.f / __shfl_sync(0xFFFFFFFFu, den, hhk[k]);
            g_agg[n * F3 + f] = acc[k] * idv;
        }
    }
}

// ================= finalize layer 3: head mean + bias + log_softmax =================
__global__ void finalize3_kernel(const float* __restrict__ b3, float* __restrict__ out) {
    int gtid = blockIdx.x * blockDim.x + threadIdx.x;
    int n = gtid >> 5;
    int lane = gtid & 31;
    if (n >= N_NODES) return;
    int c0 = lane, c1 = lane + 32;
    float v0 = -1e30f, v1 = -1e30f;
    const float* row = &g_agg[n * F3];
    if (c0 < NCLS)
        v0 = 0.25f * (row[c0] + row[NCLS + c0] + row[2 * NCLS + c0] + row[3 * NCLS + c0]) + b3[c0];
    if (c1 < NCLS)
        v1 = 0.25f * (row[c1] + row[NCLS + c1] + row[2 * NCLS + c1] + row[3 * NCLS + c1]) + b3[c1];
    float m = fmaxf(v0, v1);
#pragma unroll
    for (int o = 16; o > 0; o >>= 1) m = fmaxf(m, __shfl_xor_sync(0xFFFFFFFFu, m, o));
    float s = 0.f;
    if (c0 < NCLS) s += expf(v0 - m);
    if (c1 < NCLS) s += expf(v1 - m);
#pragma unroll
    for (int o = 16; o > 0; o >>= 1) s += __shfl_xor_sync(0xFFFFFFFFu, s, o);
    float lse = m + logf(s);
    if (c0 < NCLS) out[n * NCLS + c0] = v0 - lse;
    if (c1 < NCLS) out[n * NCLS + c1] = v1 - lse;
}

// ================= launch =================
extern "C" void kernel_launch(void* const* d_in, const int* in_sizes, int n_in,
                              void* d_out, int out_size) {
    const float* x   = (const float*)d_in[0];
    const int*   ei  = (const int*)d_in[1];   // edge_index is int32 (JAX x64 disabled)
    const float* W1  = (const float*)d_in[2];
    const float* a1s = (const float*)d_in[3];
    const float* a1d = (const float*)d_in[4];
    const float* b1  = (const float*)d_in[5];
    const float* W2  = (const float*)d_in[6];
    const float* a2s = (const float*)d_in[7];
    const float* a2d = (const float*)d_in[8];
    const float* b2  = (const float*)d_in[9];
    const float* W3  = (const float*)d_in[10];
    const float* a3s = (const float*)d_in[11];
    const float* a3d = (const float*)d_in[12];
    const float* b3  = (const float*)d_in[13];
    float* out = (float*)d_out;

    float* g_buf_ptr = nullptr;
    cudaGetSymbolAddress((void**)&g_buf_ptr, g_buf);

    // ---- build CSR once (graph identical across layers) ----
    int eb = (ET + 255) / 256;
    int nb = (N_NODES + 255) / 256;
    int scan_blocks = (N_NODES + 1023) / 1024;   // 49
    csr_init_kernel<<<nb, 256>>>();
    csr_hist_kernel<<<eb, 256>>>(ei);
    csr_scan1_kernel<<<scan_blocks, 1024>>>();
    csr_scan2_kernel<<<1, 64>>>(scan_blocks);
    csr_scan3_kernel<<<(N_NODES + 1023) / 1024, 1024>>>();
    csr_scatter_kernel<<<eb, 256>>>(ei);

    int wb = (N_NODES * 32 + 255) / 256;
    // ---- layer 1 ----
    gemm_attn_kernel<F12, F12, 32><<<N_NODES, 128>>>(x, W1, a1s, a1d);
    gat_agg128_kernel<<<wb, 256>>>(b1);
    // ---- layer 2 ----
    gemm_attn_kernel<F12, F12, 32><<<N_NODES, 128>>>(g_buf_ptr, W2, a2s, a2d);
    gat_agg128_kernel<<<wb, 256>>>(b2);
    // ---- layer 3 ----
    gemm_attn_kernel<F12, F3, NCLS><<<N_NODES, 192>>>(g_buf_ptr, W3, a3s, a3d);
    gat_agg188_kernel<<<wb, 256>>>();
    finalize3_kernel<<<wb, 256>>>(b3, out);
}

// round 5
// speedup vs baseline: 1.6910x; 1.1322x over previous
#include <cuda_runtime.h>

#define N_NODES 50000
#define N_EDGES 800000
#define ET      (N_EDGES + N_NODES)   // 850000 edges incl self loops
#define HEADS   4
#define F12     128                    // 4*32
#define F3      188                    // 4*47
#define NCLS    47
#define NEG_SLOPE 0.2f

// ---------------- scratch (device globals, no allocation) ----------------
__device__ float g_h[N_NODES * F3];        // linear output of current layer
__device__ float g_buf[N_NODES * F12];     // activations between layers
__device__ float g_agg[N_NODES * F3];      // layer-3 aggregation (pre-mean)
__device__ float g_asrc[N_NODES * HEADS];
__device__ float g_adst[N_NODES * HEADS];
__device__ float g_w[(size_t)ET * HEADS];  // per-edge raw alpha/exp (per dst list)
// CSR by destination
__device__ int g_deg[N_NODES];
__device__ int g_rowptr[N_NODES + 1];
__device__ int g_cursor[N_NODES];
__device__ int g_col[ET];                  // src node per slot
__device__ int g_bsum[64];
__device__ int g_boff[64];

// ================= CSR build =================
__global__ void csr_init_kernel() {
    int i = blockIdx.x * blockDim.x + threadIdx.x;
    if (i < N_NODES) { g_deg[i] = 0; g_cursor[i] = 0; }
}

__global__ void csr_hist_kernel(const int* __restrict__ ei) {
    int e = blockIdx.x * blockDim.x + threadIdx.x;
    if (e >= ET) return;
    int dst = (e < N_EDGES) ? ei[N_EDGES + e] : (e - N_EDGES);
    atomicAdd(&g_deg[dst], 1);
}

__global__ void csr_scan1_kernel() {
    __shared__ int s[1024];
    int t = threadIdx.x;
    int i = blockIdx.x * 1024 + t;
    int v = (i < N_NODES) ? g_deg[i] : 0;
    s[t] = v;
    __syncthreads();
#pragma unroll
    for (int off = 1; off < 1024; off <<= 1) {
        int x = (t >= off) ? s[t - off] : 0;
        __syncthreads();
        s[t] += x;
        __syncthreads();
    }
    if (i <= N_NODES) g_rowptr[i] = s[t] - v;   // exclusive
    if (t == 1023) g_bsum[blockIdx.x] = s[t];
}

__global__ void csr_scan2_kernel(int nblocks) {
    __shared__ int s[64];
    int t = threadIdx.x;
    int v = (t < nblocks) ? g_bsum[t] : 0;
    s[t] = v;
    __syncthreads();
#pragma unroll
    for (int off = 1; off < 64; off <<= 1) {
        int x = (t >= off) ? s[t - off] : 0;
        __syncthreads();
        s[t] += x;
        __syncthreads();
    }
    if (t < nblocks) g_boff[t] = s[t] - v;      // exclusive
}

__global__ void csr_scan3_kernel() {
    int i = blockIdx.x * blockDim.x + threadIdx.x;
    if (i < N_NODES) g_rowptr[i] += g_boff[i >> 10];
    if (i == 0) g_rowptr[N_NODES] = ET;
}

__global__ void csr_scatter_kernel(const int* __restrict__ ei) {
    int e = blockIdx.x * blockDim.x + threadIdx.x;
    if (e >= ET) return;
    int src, dst;
    if (e < N_EDGES) { src = ei[e]; dst = ei[N_EDGES + e]; }
    else             { src = dst = e - N_EDGES; }
    int pos = atomicAdd(&g_cursor[dst], 1);
    g_col[g_rowptr[dst] + pos] = src;
}

// ================= register-tiled GEMM: g_h = x @ W =================
// 64 nodes x FOUT_PAD per block; 8x8 micro-tile per thread; k-tiled by 32.
// FIN is always 128.
template <int FOUT_PAD, int FOUT_REAL>
__global__ void gemm_tile_kernel(const float* __restrict__ x,
                                 const float* __restrict__ W) {
    const int FT = FOUT_PAD / 8;            // f-thread count (16 or 24)
    const int NTHREADS = FT * 8;
    __shared__ float ws[32][FOUT_PAD];
    __shared__ float xs[64][33];
    int tid = threadIdx.x;
    int ft = tid % FT;
    int nt = tid / FT;                       // 0..7
    int n0 = blockIdx.x * 64;

    float acc[8][8];
#pragma unroll
    for (int i = 0; i < 8; i++)
#pragma unroll
        for (int j = 0; j < 8; j++) acc[i][j] = 0.f;

    for (int kt = 0; kt < 128; kt += 32) {
        for (int idx = tid; idx < 64 * 32; idx += NTHREADS) {
            int r = idx >> 5, c = idx & 31;
            int n = n0 + r;
            xs[r][c] = (n < N_NODES) ? x[n * 128 + kt + c] : 0.f;
        }
        for (int idx = tid; idx < 32 * FOUT_PAD; idx += NTHREADS) {
            int r = idx / FOUT_PAD, c = idx % FOUT_PAD;
            ws[r][c] = (c < FOUT_REAL) ? W[(kt + r) * FOUT_REAL + c] : 0.f;
        }
        __syncthreads();
#pragma unroll
        for (int kk = 0; kk < 32; kk++) {
            float wv[8], xv[8];
#pragma unroll
            for (int j = 0; j < 8; j++) wv[j] = ws[kk][ft * 8 + j];
#pragma unroll
            for (int i = 0; i < 8; i++) xv[i] = xs[nt * 8 + i][kk];
#pragma unroll
            for (int i = 0; i < 8; i++)
#pragma unroll
                for (int j = 0; j < 8; j++)
                    acc[i][j] = fmaf(xv[i], wv[j], acc[i][j]);
        }
        __syncthreads();
    }
#pragma unroll
    for (int i = 0; i < 8; i++) {
        int n = n0 + nt * 8 + i;
        if (n < N_NODES) {
#pragma unroll
            for (int j = 0; j < 8; j++) {
                int f = ft * 8 + j;
                if (f < FOUT_REAL) g_h[n * FOUT_REAL + f] = acc[i][j];
            }
        }
    }
}

// ================= attention coefficients from g_h =================
template <int FOUT, int C>
__global__ void attn_coef_kernel(const float* __restrict__ as,
                                 const float* __restrict__ ad) {
    __shared__ float s_s[HEADS], s_d[HEADS];
    int n = blockIdx.x;
    int f = threadIdx.x;
    if (f < HEADS) { s_s[f] = 0.f; s_d[f] = 0.f; }
    __syncthreads();
    if (f < FOUT) {
        float h = g_h[n * FOUT + f];
        int hh = f / C;
        atomicAdd(&s_s[hh], h * as[f]);
        atomicAdd(&s_d[hh], h * ad[f]);
    }
    __syncthreads();
    if (f < HEADS) {
        g_asrc[n * HEADS + f] = s_s[f];
        g_adst[n * HEADS + f] = s_d[f];
    }
}

// ================= fused softmax + gather-aggregate =================
// one warp per destination node. No global atomics.
__global__ void gat_agg128_kernel(const float* __restrict__ bias) {
    int gtid = blockIdx.x * blockDim.x + threadIdx.x;
    int n = gtid >> 5;
    int lane = gtid & 31;
    if (n >= N_NODES) return;
    int beg = g_rowptr[n];
    int deg = g_rowptr[n + 1] - beg;
    int hme = lane & 3;
    float adst_h = g_adst[n * HEADS + hme];

    // pass 1: alpha (stored raw) + max
    float mx = -1e30f;
    for (int p = lane; p < deg * HEADS; p += 32) {
        int src = g_col[beg + (p >> 2)];
        float a = g_asrc[src * HEADS + hme] + adst_h;
        a = (a >= 0.f) ? a : NEG_SLOPE * a;
        g_w[(size_t)(beg << 2) + p] = a;
        mx = fmaxf(mx, a);
    }
    mx = fmaxf(mx, __shfl_xor_sync(0xFFFFFFFFu, mx, 4));
    mx = fmaxf(mx, __shfl_xor_sync(0xFFFFFFFFu, mx, 8));
    mx = fmaxf(mx, __shfl_xor_sync(0xFFFFFFFFu, mx, 16));

    // pass 2: sequential exp + denom
    float den = 0.f;
    for (int p = lane; p < deg * HEADS; p += 32) {
        float w = __expf(g_w[(size_t)(beg << 2) + p] - mx);
        g_w[(size_t)(beg << 2) + p] = w;
        den += w;
    }
    den += __shfl_xor_sync(0xFFFFFFFFu, den, 4);
    den += __shfl_xor_sync(0xFFFFFFFFu, den, 8);
    den += __shfl_xor_sync(0xFFFFFFFFu, den, 16);
    __syncwarp();

    // pass 3: gather-accumulate. lane owns feats [4*lane,4*lane+4), head = lane>>3
    int hh = lane >> 3;
    float4 acc = make_float4(0.f, 0.f, 0.f, 0.f);
#pragma unroll 4
    for (int i = 0; i < deg; i++) {
        int src = g_col[beg + i];
        float4 w4 = *(const float4*)&g_w[(size_t)(beg + i) * 4];
        float w = (hh == 0) ? w4.x : (hh == 1) ? w4.y : (hh == 2) ? w4.z : w4.w;
        float4 v = *(const float4*)&g_h[src * F12 + 4 * lane];
        acc.x = fmaf(v.x, w, acc.x);
        acc.y = fmaf(v.y, w, acc.y);
        acc.z = fmaf(v.z, w, acc.z);
        acc.w = fmaf(v.w, w, acc.w);
    }
    float idv = 1.f / __shfl_sync(0xFFFFFFFFu, den, hh);
    float4 b4 = *(const float4*)&bias[4 * lane];
    float4 o;
    o.x = fmaxf(fmaf(acc.x, idv, b4.x), 0.f);
    o.y = fmaxf(fmaf(acc.y, idv, b4.y), 0.f);
    o.z = fmaxf(fmaf(acc.z, idv, b4.z), 0.f);
    o.w = fmaxf(fmaf(acc.w, idv, b4.w), 0.f);
    *(float4*)&g_buf[n * F12 + 4 * lane] = o;
}

// layer 3 variant: FT=188, C=47; lane owns feats lane+32k (k<6); writes g_agg.
__global__ void gat_agg188_kernel() {
    int gtid = blockIdx.x * blockDim.x + threadIdx.x;
    int n = gtid >> 5;
    int lane = gtid & 31;
    if (n >= N_NODES) return;
    int beg = g_rowptr[n];
    int deg = g_rowptr[n + 1] - beg;
    int hme = lane & 3;
    float adst_h = g_adst[n * HEADS + hme];

    float mx = -1e30f;
    for (int p = lane; p < deg * HEADS; p += 32) {
        int src = g_col[beg + (p >> 2)];
        float a = g_asrc[src * HEADS + hme] + adst_h;
        a = (a >= 0.f) ? a : NEG_SLOPE * a;
        g_w[(size_t)(beg << 2) + p] = a;
        mx = fmaxf(mx, a);
    }
    mx = fmaxf(mx, __shfl_xor_sync(0xFFFFFFFFu, mx, 4));
    mx = fmaxf(mx, __shfl_xor_sync(0xFFFFFFFFu, mx, 8));
    mx = fmaxf(mx, __shfl_xor_sync(0xFFFFFFFFu, mx, 16));

    float den = 0.f;
    for (int p = lane; p < deg * HEADS; p += 32) {
        float w = __expf(g_w[(size_t)(beg << 2) + p] - mx);
        g_w[(size_t)(beg << 2) + p] = w;
        den += w;
    }
    den += __shfl_xor_sync(0xFFFFFFFFu, den, 4);
    den += __shfl_xor_sync(0xFFFFFFFFu, den, 8);
    den += __shfl_xor_sync(0xFFFFFFFFu, den, 16);
    __syncwarp();

    int hhk[6];
#pragma unroll
    for (int k = 0; k < 6; k++) hhk[k] = (lane + 32 * k) / NCLS;
    float acc[6] = {0.f, 0.f, 0.f, 0.f, 0.f, 0.f};
#pragma unroll 2
    for (int i = 0; i < deg; i++) {
        int src = g_col[beg + i];
        float4 w4 = *(const float4*)&g_w[(size_t)(beg + i) * 4];
        const float* hrow = &g_h[src * F3];
#pragma unroll
        for (int k = 0; k < 6; k++) {
            int f = lane + 32 * k;
            if (f < F3) {
                int hh = hhk[k];
                float w = (hh == 0) ? w4.x : (hh == 1) ? w4.y : (hh == 2) ? w4.z : w4.w;
                acc[k] = fmaf(hrow[f], w, acc[k]);
            }
        }
    }
#pragma unroll
    for (int k = 0; k < 6; k++) {
        int f = lane + 32 * k;
        if (f < F3) {
            float idv = 1.f / __shfl_sync(0xFFFFFFFFu, den, hhk[k]);
            g_agg[n * F3 + f] = acc[k] * idv;
        }
    }
}

// ================= finalize layer 3: head mean + bias + log_softmax =================
__global__ void finalize3_kernel(const float* __restrict__ b3, float* __restrict__ out) {
    int gtid = blockIdx.x * blockDim.x + threadIdx.x;
    int n = gtid >> 5;
    int lane = gtid & 31;
    if (n >= N_NODES) return;
    int c0 = lane, c1 = lane + 32;
    float v0 = -1e30f, v1 = -1e30f;
    const float* row = &g_agg[n * F3];
    if (c0 < NCLS)
        v0 = 0.25f * (row[c0] + row[NCLS + c0] + row[2 * NCLS + c0] + row[3 * NCLS + c0]) + b3[c0];
    if (c1 < NCLS)
        v1 = 0.25f * (row[c1] + row[NCLS + c1] + row[2 * NCLS + c1] + row[3 * NCLS + c1]) + b3[c1];
    float m = fmaxf(v0, v1);
#pragma unroll
    for (int o = 16; o > 0; o >>= 1) m = fmaxf(m, __shfl_xor_sync(0xFFFFFFFFu, m, o));
    float s = 0.f;
    if (c0 < NCLS) s += expf(v0 - m);
    if (c1 < NCLS) s += expf(v1 - m);
#pragma unroll
    for (int o = 16; o > 0; o >>= 1) s += __shfl_xor_sync(0xFFFFFFFFu, s, o);
    float lse = m + logf(s);
    if (c0 < NCLS) out[n * NCLS + c0] = v0 - lse;
    if (c1 < NCLS) out[n * NCLS + c1] = v1 - lse;
}

// ================= launch =================
extern "C" void kernel_launch(void* const* d_in, const int* in_sizes, int n_in,
                              void* d_out, int out_size) {
    const float* x   = (const float*)d_in[0];
    const int*   ei  = (const int*)d_in[1];   // edge_index is int32 (JAX x64 disabled)
    const float* W1  = (const float*)d_in[2];
    const float* a1s = (const float*)d_in[3];
    const float* a1d = (const float*)d_in[4];
    const float* b1  = (const float*)d_in[5];
    const float* W2  = (const float*)d_in[6];
    const float* a2s = (const float*)d_in[7];
    const float* a2d = (const float*)d_in[8];
    const float* b2  = (const float*)d_in[9];
    const float* W3  = (const float*)d_in[10];
    const float* a3s = (const float*)d_in[11];
    const float* a3d = (const float*)d_in[12];
    const float* b3  = (const float*)d_in[13];
    float* out = (float*)d_out;

    float* g_buf_ptr = nullptr;
    cudaGetSymbolAddress((void**)&g_buf_ptr, g_buf);

    // ---- build CSR once (graph identical across layers) ----
    int eb = (ET + 255) / 256;
    int nb = (N_NODES + 255) / 256;
    int scan_blocks = (N_NODES + 1023) / 1024;   // 49
    csr_init_kernel<<<nb, 256>>>();
    csr_hist_kernel<<<eb, 256>>>(ei);
    csr_scan1_kernel<<<scan_blocks, 1024>>>();
    csr_scan2_kernel<<<1, 64>>>(scan_blocks);
    csr_scan3_kernel<<<(N_NODES + 1023) / 1024, 1024>>>();
    csr_scatter_kernel<<<eb, 256>>>(ei);

    int gemm_blocks = (N_NODES + 63) / 64;       // 782
    int wb = (N_NODES * 32 + 255) / 256;
    // ---- layer 1 ----
    gemm_tile_kernel<128, 128><<<gemm_blocks, 128>>>(x, W1);
    attn_coef_kernel<F12, 32><<<N_NODES, 128>>>(a1s, a1d);
    gat_agg128_kernel<<<wb, 256>>>(b1);
    // ---- layer 2 ----
    gemm_tile_kernel<128, 128><<<gemm_blocks, 128>>>(g_buf_ptr, W2);
    attn_coef_kernel<F12, 32><<<N_NODES, 128>>>(a2s, a2d);
    gat_agg128_kernel<<<wb, 256>>>(b2);
    // ---- layer 3 ----
    gemm_tile_kernel<192, 188><<<gemm_blocks, 192>>>(g_buf_ptr, W3);
    attn_coef_kernel<F3, NCLS><<<N_NODES, 192>>>(a3s, a3d);
    gat_agg188_kernel<<<wb, 256>>>();
    finalize3_kernel<<<wb, 256>>>(b3, out);
}

// round 6
// speedup vs baseline: 1.9823x; 1.1723x over previous
#include <cuda_runtime.h>

#define N_NODES 50000
#define N_EDGES 800000
#define ET      (N_EDGES + N_NODES)   // 850000 edges incl self loops
#define HEADS   4
#define F12     128                    // 4*32
#define F3      188                    // 4*47
#define NCLS    47
#define NEG_SLOPE 0.2f

// ---------------- scratch (device globals, no allocation) ----------------
// NOTE: g_deg and g_flag are zero at module load and re-zeroed at the end of
// every kernel_launch (tail of finalize3), so each call sees zeroed state.
__device__ float g_h[N_NODES * F3];        // linear output of current layer
__device__ float g_buf[N_NODES * F12];     // activations between layers
__device__ float g_agg[N_NODES * F3];      // layer-3 aggregation (pre-mean)
__device__ float g_asrc[N_NODES * HEADS];
__device__ float g_adst[N_NODES * HEADS];
__device__ int g_deg[N_NODES];
__device__ int g_rowptr[N_NODES + 1];
__device__ int g_cursor[N_NODES];
__device__ int g_col[ET];                  // src node per CSR slot
__device__ int g_carry[64];
__device__ int g_flag[64];

// ================= CSR build =================
__global__ void csr_hist_kernel(const int* __restrict__ ei) {
    int e = blockIdx.x * blockDim.x + threadIdx.x;
    if (e >= ET) return;
    int dst = (e < N_EDGES) ? ei[N_EDGES + e] : (e - N_EDGES);
    atomicAdd(&g_deg[dst], 1);
}

// single-kernel chained scan: 49 blocks x 1024; also zeroes g_cursor.
__global__ void csr_scan_kernel() {
    __shared__ int s[1024];
    __shared__ int s_carry;
    int b = blockIdx.x, t = threadIdx.x;
    int i = b * 1024 + t;
    if (i < N_NODES) g_cursor[i] = 0;
    int v = (i < N_NODES) ? g_deg[i] : 0;
    s[t] = v;
    __syncthreads();
#pragma unroll
    for (int off = 1; off < 1024; off <<= 1) {
        int x = (t >= off) ? s[t - off] : 0;
        __syncthreads();
        s[t] += x;
        __syncthreads();
    }
    int incl = s[t];
    int total = s[1023];
    if (t == 0) {
        int carry = 0;
        if (b > 0) {
            while (atomicAdd(&g_flag[b - 1], 0) == 0) { }
            carry = g_carry[b - 1];
        }
        s_carry = carry;
        g_carry[b] = carry + total;
        __threadfence();
        atomicExch(&g_flag[b], 1);
    }
    __syncthreads();
    int carry = s_carry;
    if (i <= N_NODES) g_rowptr[i] = carry + incl - v;   // exclusive prefix
}

__global__ void csr_scatter_kernel(const int* __restrict__ ei) {
    int e = blockIdx.x * blockDim.x + threadIdx.x;
    if (e >= ET) return;
    int src, dst;
    if (e < N_EDGES) { src = ei[e]; dst = ei[N_EDGES + e]; }
    else             { src = dst = e - N_EDGES; }
    int pos = atomicAdd(&g_cursor[dst], 1);
    g_col[g_rowptr[dst] + pos] = src;
}

// ================= register-tiled GEMM: g_h = x @ W =================
// 64 nodes x FOUT_PAD per block; 8x8 micro-tile per thread; k-tiled by 32.
template <int FOUT_PAD, int FOUT_REAL>
__global__ void gemm_tile_kernel(const float* __restrict__ x,
                                 const float* __restrict__ W) {
    const int FT = FOUT_PAD / 8;            // f-thread count (16 or 24)
    const int NTHREADS = FT * 8;
    __shared__ float ws[32][FOUT_PAD];
    __shared__ float xs[64][33];
    int tid = threadIdx.x;
    int ft = tid % FT;
    int nt = tid / FT;                       // 0..7
    int n0 = blockIdx.x * 64;

    float acc[8][8];
#pragma unroll
    for (int i = 0; i < 8; i++)
#pragma unroll
        for (int j = 0; j < 8; j++) acc[i][j] = 0.f;

    for (int kt = 0; kt < 128; kt += 32) {
        for (int idx = tid; idx < 64 * 32; idx += NTHREADS) {
            int r = idx >> 5, c = idx & 31;
            int n = n0 + r;
            xs[r][c] = (n < N_NODES) ? x[n * 128 + kt + c] : 0.f;
        }
        for (int idx = tid; idx < 32 * FOUT_PAD; idx += NTHREADS) {
            int r = idx / FOUT_PAD, c = idx % FOUT_PAD;
            ws[r][c] = (c < FOUT_REAL) ? W[(kt + r) * FOUT_REAL + c] : 0.f;
        }
        __syncthreads();
#pragma unroll
        for (int kk = 0; kk < 32; kk++) {
            float wv[8], xv[8];
#pragma unroll
            for (int j = 0; j < 8; j++) wv[j] = ws[kk][ft * 8 + j];
#pragma unroll
            for (int i = 0; i < 8; i++) xv[i] = xs[nt * 8 + i][kk];
#pragma unroll
            for (int i = 0; i < 8; i++)
#pragma unroll
                for (int j = 0; j < 8; j++)
                    acc[i][j] = fmaf(xv[i], wv[j], acc[i][j]);
        }
        __syncthreads();
    }
#pragma unroll
    for (int i = 0; i < 8; i++) {
        int n = n0 + nt * 8 + i;
        if (n < N_NODES) {
#pragma unroll
            for (int j = 0; j < 8; j++) {
                int f = ft * 8 + j;
                if (f < FOUT_REAL) g_h[n * FOUT_REAL + f] = acc[i][j];
            }
        }
    }
}

// ================= attention coefficients (warp per node) =================
__global__ void attn_coef128_kernel(const float* __restrict__ as,
                                    const float* __restrict__ ad) {
    int gtid = blockIdx.x * blockDim.x + threadIdx.x;
    int n = gtid >> 5;
    int lane = gtid & 31;
    if (n >= N_NODES) return;
    float4 v  = *(const float4*)&g_h[n * F12 + 4 * lane];
    float4 a4 = *(const float4*)&as[4 * lane];
    float4 d4 = *(const float4*)&ad[4 * lane];
    float ps = v.x * a4.x + v.y * a4.y + v.z * a4.z + v.w * a4.w;
    float pd = v.x * d4.x + v.y * d4.y + v.z * d4.z + v.w * d4.w;
    // reduce within 8-lane head group (xor 1,2,4 stay in group)
    ps += __shfl_xor_sync(0xFFFFFFFFu, ps, 1);
    pd += __shfl_xor_sync(0xFFFFFFFFu, pd, 1);
    ps += __shfl_xor_sync(0xFFFFFFFFu, ps, 2);
    pd += __shfl_xor_sync(0xFFFFFFFFu, pd, 2);
    ps += __shfl_xor_sync(0xFFFFFFFFu, ps, 4);
    pd += __shfl_xor_sync(0xFFFFFFFFu, pd, 4);
    if ((lane & 7) == 0) {
        g_asrc[n * HEADS + (lane >> 3)] = ps;
        g_adst[n * HEADS + (lane >> 3)] = pd;
    }
}

__global__ void attn_coef188_kernel(const float* __restrict__ as,
                                    const float* __restrict__ ad) {
    int gtid = blockIdx.x * blockDim.x + threadIdx.x;
    int n = gtid >> 5;
    int lane = gtid & 31;
    if (n >= N_NODES) return;
    float hs[HEADS] = {0.f, 0.f, 0.f, 0.f};
    float hd[HEADS] = {0.f, 0.f, 0.f, 0.f};
#pragma unroll
    for (int k = 0; k < 6; k++) {
        int f = lane + 32 * k;
        if (f < F3) {
            float v = g_h[n * F3 + f];
            int hh = f / NCLS;
            hs[hh] = fmaf(v, as[f], hs[hh]);
            hd[hh] = fmaf(v, ad[f], hd[hh]);
        }
    }
#pragma unroll
    for (int h = 0; h < HEADS; h++) {
#pragma unroll
        for (int o = 16; o > 0; o >>= 1) {
            hs[h] += __shfl_xor_sync(0xFFFFFFFFu, hs[h], o);
            hd[h] += __shfl_xor_sync(0xFFFFFFFFu, hd[h], o);
        }
    }
    if (lane < HEADS) {
        g_asrc[n * HEADS + lane] = hs[lane];
        g_adst[n * HEADS + lane] = hd[lane];
    }
}

// ================= fused flash-style softmax + gather-aggregate =================
// ONE pass per layer. warp per dst node; lane owns feats [4*lane,4*lane+4),
// head hh = lane>>3. Online softmax: running (m, den), acc rescaled on the fly.
__global__ void gat_agg128_kernel(const float* __restrict__ bias) {
    int gtid = blockIdx.x * blockDim.x + threadIdx.x;
    int n = gtid >> 5;
    int lane = gtid & 31;
    if (n >= N_NODES) return;
    int beg = g_rowptr[n];
    int deg = g_rowptr[n + 1] - beg;
    int hh = lane >> 3;
    const float4 adst4 = *(const float4*)&g_adst[n * HEADS];
    float adst_h = (hh == 0) ? adst4.x : (hh == 1) ? adst4.y : (hh == 2) ? adst4.z : adst4.w;

    float m = -1e30f, den = 0.f;
    float4 acc = make_float4(0.f, 0.f, 0.f, 0.f);
#pragma unroll 4
    for (int i = 0; i < deg; i++) {
        int src = g_col[beg + i];
        float4 s4 = *(const float4*)&g_asrc[src * HEADS];   // broadcast across warp
        float a = ((hh == 0) ? s4.x : (hh == 1) ? s4.y : (hh == 2) ? s4.z : s4.w) + adst_h;
        a = (a >= 0.f) ? a : NEG_SLOPE * a;
        float mn = fmaxf(m, a);
        float sc = __expf(m - mn);
        float e  = __expf(a - mn);
        m = mn;
        den = fmaf(den, sc, e);
        float4 v = *(const float4*)&g_h[src * F12 + 4 * lane];
        acc.x = fmaf(acc.x, sc, v.x * e);
        acc.y = fmaf(acc.y, sc, v.y * e);
        acc.z = fmaf(acc.z, sc, v.z * e);
        acc.w = fmaf(acc.w, sc, v.w * e);
    }
    float idv = 1.f / den;
    float4 b4 = *(const float4*)&bias[4 * lane];
    float4 o;
    o.x = fmaxf(fmaf(acc.x, idv, b4.x), 0.f);
    o.y = fmaxf(fmaf(acc.y, idv, b4.y), 0.f);
    o.z = fmaxf(fmaf(acc.z, idv, b4.z), 0.f);
    o.w = fmaxf(fmaf(acc.w, idv, b4.w), 0.f);
    *(float4*)&g_buf[n * F12 + 4 * lane] = o;
}

// layer 3 variant: lane owns feats lane+32k (k<6) spanning multiple heads;
// per-lane online softmax state for all 4 heads.
__global__ void gat_agg188_kernel() {
    int gtid = blockIdx.x * blockDim.x + threadIdx.x;
    int n = gtid >> 5;
    int lane = gtid & 31;
    if (n >= N_NODES) return;
    int beg = g_rowptr[n];
    int deg = g_rowptr[n + 1] - beg;
    const float4 adst4 = *(const float4*)&g_adst[n * HEADS];

    int hhk[6];
#pragma unroll
    for (int k = 0; k < 6; k++) hhk[k] = (lane + 32 * k) / NCLS;

    float m[HEADS] = {-1e30f, -1e30f, -1e30f, -1e30f};
    float den[HEADS] = {0.f, 0.f, 0.f, 0.f};
    float acc[6] = {0.f, 0.f, 0.f, 0.f, 0.f, 0.f};

#pragma unroll 2
    for (int i = 0; i < deg; i++) {
        int src = g_col[beg + i];
        float4 s4 = *(const float4*)&g_asrc[src * HEADS];
        float al[HEADS] = {s4.x + adst4.x, s4.y + adst4.y, s4.z + adst4.z, s4.w + adst4.w};
        float e[HEADS], sc[HEADS];
#pragma unroll
        for (int h = 0; h < HEADS; h++) {
            float a = al[h];
            a = (a >= 0.f) ? a : NEG_SLOPE * a;
            float mn = fmaxf(m[h], a);
            sc[h] = __expf(m[h] - mn);
            e[h]  = __expf(a - mn);
            m[h] = mn;
            den[h] = fmaf(den[h], sc[h], e[h]);
        }
        const float* hrow = &g_h[src * F3];
#pragma unroll
        for (int k = 0; k < 6; k++) {
            int f = lane + 32 * k;
            if (f < F3) {
                int hh = hhk[k];
                acc[k] = fmaf(acc[k], sc[hh], hrow[f] * e[hh]);
            }
        }
    }
#pragma unroll
    for (int k = 0; k < 6; k++) {
        int f = lane + 32 * k;
        if (f < F3) g_agg[n * F3 + f] = acc[k] / den[hhk[k]];
    }
}

// ================= finalize layer 3: head mean + bias + log_softmax =================
// tail: re-zero g_deg / g_flag for the next call (determinism invariant).
__global__ void finalize3_kernel(const float* __restrict__ b3, float* __restrict__ out) {
    int gtid = blockIdx.x * blockDim.x + threadIdx.x;
    if (gtid < N_NODES) g_deg[gtid] = 0;
    if (gtid < 64) { g_flag[gtid] = 0; g_carry[gtid] = 0; }
    int n = gtid >> 5;
    int lane = gtid & 31;
    if (n >= N_NODES) return;
    int c0 = lane, c1 = lane + 32;
    float v0 = -1e30f, v1 = -1e30f;
    const float* row = &g_agg[n * F3];
    if (c0 < NCLS)
        v0 = 0.25f * (row[c0] + row[NCLS + c0] + row[2 * NCLS + c0] + row[3 * NCLS + c0]) + b3[c0];
    if (c1 < NCLS)
        v1 = 0.25f * (row[c1] + row[NCLS + c1] + row[2 * NCLS + c1] + row[3 * NCLS + c1]) + b3[c1];
    float mm = fmaxf(v0, v1);
#pragma unroll
    for (int o = 16; o > 0; o >>= 1) mm = fmaxf(mm, __shfl_xor_sync(0xFFFFFFFFu, mm, o));
    float s = 0.f;
    if (c0 < NCLS) s += expf(v0 - mm);
    if (c1 < NCLS) s += expf(v1 - mm);
#pragma unroll
    for (int o = 16; o > 0; o >>= 1) s += __shfl_xor_sync(0xFFFFFFFFu, s, o);
    float lse = mm + logf(s);
    if (c0 < NCLS) out[n * NCLS + c0] = v0 - lse;
    if (c1 < NCLS) out[n * NCLS + c1] = v1 - lse;
}

// ================= launch =================
extern "C" void kernel_launch(void* const* d_in, const int* in_sizes, int n_in,
                              void* d_out, int out_size) {
    const float* x   = (const float*)d_in[0];
    const int*   ei  = (const int*)d_in[1];   // edge_index is int32 (JAX x64 disabled)
    const float* W1  = (const float*)d_in[2];
    const float* a1s = (const float*)d_in[3];
    const float* a1d = (const float*)d_in[4];
    const float* b1  = (const float*)d_in[5];
    const float* W2  = (const float*)d_in[6];
    const float* a2s = (const float*)d_in[7];
    const float* a2d = (const float*)d_in[8];
    const float* b2  = (const float*)d_in[9];
    const float* W3  = (const float*)d_in[10];
    const float* a3s = (const float*)d_in[11];
    const float* a3d = (const float*)d_in[12];
    const float* b3  = (const float*)d_in[13];
    float* out = (float*)d_out;

    float* g_buf_ptr = nullptr;
    cudaGetSymbolAddress((void**)&g_buf_ptr, g_buf);

    int eb = (ET + 255) / 256;
    int gemm_blocks = (N_NODES + 63) / 64;       // 782
    int wb = (N_NODES * 32 + 255) / 256;

    // CSR build (g_deg/g_flag pre-zeroed: module load + finalize3 tail)
    csr_hist_kernel<<<eb, 256>>>(ei);                       // launch 0
    csr_scan_kernel<<<49, 1024>>>();                        // launch 1
    csr_scatter_kernel<<<eb, 256>>>(ei);                    // launch 2
    // layer 1
    gemm_tile_kernel<128, 128><<<gemm_blocks, 128>>>(x, W1);   // launch 3 (profiled)
    attn_coef128_kernel<<<wb, 256>>>(a1s, a1d);             // launch 4
    gat_agg128_kernel<<<wb, 256>>>(b1);                     // launch 5
    // layer 2
    gemm_tile_kernel<128, 128><<<gemm_blocks, 128>>>(g_buf_ptr, W2);
    attn_coef128_kernel<<<wb, 256>>>(a2s, a2d);
    gat_agg128_kernel<<<wb, 256>>>(b2);
    // layer 3
    gemm_tile_kernel<192, 188><<<gemm_blocks, 192>>>(g_buf_ptr, W3);
    attn_coef188_kernel<<<wb, 256>>>(a3s, a3d);
    gat_agg188_kernel<<<wb, 256>>>();
    finalize3_kernel<<<wb, 256>>>(b3, out);
}

// round 7
// speedup vs baseline: 3.2178x; 1.6233x over previous
#include <cuda_runtime.h>

#define N_NODES 50000
#define N_EDGES 800000
#define ET      (N_EDGES + N_NODES)   // 850000 edges incl self loops
#define HEADS   4
#define F12     128                    // 4*32
#define F3      188                    // 4*47
#define NCLS    47
#define NEG_SLOPE 0.2f

// ---------------- scratch (device globals, no allocation) ----------------
// g_deg/g_flag/g_carry zero at module load; re-zeroed in finalize3 tail.
__device__ float g_h[N_NODES * F3];        // linear output of current layer
__device__ float g_buf[N_NODES * F12];     // activations between layers
__device__ float g_agg[N_NODES * F3];      // layer-3 aggregation (pre-mean)
__device__ float g_asrc[N_NODES * HEADS];
__device__ float g_adst[N_NODES * HEADS];
__device__ int g_deg[N_NODES];
__device__ int g_rowptr[N_NODES + 1];
__device__ int g_cursor[N_NODES];
__device__ int g_col[ET];                  // src node per CSR slot
__device__ int g_carry[64];
__device__ int g_flag[64];

// ================= CSR build =================
__global__ void csr_hist_kernel(const int* __restrict__ ei) {
    int e = blockIdx.x * blockDim.x + threadIdx.x;
    if (e >= ET) return;
    int dst = (e < N_EDGES) ? ei[N_EDGES + e] : (e - N_EDGES);
    atomicAdd(&g_deg[dst], 1);
}

// single-kernel chained scan: 49 blocks x 1024; also zeroes g_cursor.
__global__ void csr_scan_kernel() {
    __shared__ int s[1024];
    __shared__ int s_carry;
    int b = blockIdx.x, t = threadIdx.x;
    int i = b * 1024 + t;
    if (i < N_NODES) g_cursor[i] = 0;
    int v = (i < N_NODES) ? g_deg[i] : 0;
    s[t] = v;
    __syncthreads();
#pragma unroll
    for (int off = 1; off < 1024; off <<= 1) {
        int x = (t >= off) ? s[t - off] : 0;
        __syncthreads();
        s[t] += x;
        __syncthreads();
    }
    int incl = s[t];
    int total = s[1023];
    if (t == 0) {
        int carry = 0;
        if (b > 0) {
            while (atomicAdd(&g_flag[b - 1], 0) == 0) { }
            carry = g_carry[b - 1];
        }
        s_carry = carry;
        g_carry[b] = carry + total;
        __threadfence();
        atomicExch(&g_flag[b], 1);
    }
    __syncthreads();
    int carry = s_carry;
    if (i <= N_NODES) g_rowptr[i] = carry + incl - v;   // exclusive prefix
}

__global__ void csr_scatter_kernel(const int* __restrict__ ei) {
    int e = blockIdx.x * blockDim.x + threadIdx.x;
    if (e >= ET) return;
    int src, dst;
    if (e < N_EDGES) { src = ei[e]; dst = ei[N_EDGES + e]; }
    else             { src = dst = e - N_EDGES; }
    int pos = atomicAdd(&g_cursor[dst], 1);
    g_col[g_rowptr[dst] + pos] = src;
}

// ================= register-tiled GEMM: g_h = x @ W =================
// 64 nodes x (32*TN) feats per block, 256 threads, 8x TN micro-tile.
// ft = tid&31 owns feats [ft*TN, ft*TN+TN); nt = tid>>5 owns nodes nt*8..+8.
template <int TN, int FOUT_REAL>
__global__ __launch_bounds__(256) void gemm_tile_kernel(const float* __restrict__ x,
                                                        const float* __restrict__ W) {
    const int FOUT_PAD = 32 * TN;
    __shared__ float ws[32][FOUT_PAD];
    __shared__ float xs[64][36];
    int tid = threadIdx.x;
    int ft = tid & 31;
    int nt = tid >> 5;
    int n0 = blockIdx.x * 64;

    float acc[8][TN];
#pragma unroll
    for (int i = 0; i < 8; i++)
#pragma unroll
        for (int j = 0; j < TN; j++) acc[i][j] = 0.f;

    for (int kt = 0; kt < 128; kt += 32) {
        // x tile: 64x32 = 512 float4 loads
#pragma unroll
        for (int idx = tid; idx < 512; idx += 256) {
            int r = idx >> 3, c4 = idx & 7;
            int n = n0 + r;
            float4 v = (n < N_NODES) ? *(const float4*)&x[n * 128 + kt + c4 * 4]
                                     : make_float4(0.f, 0.f, 0.f, 0.f);
            *(float4*)&xs[r][c4 * 4] = v;
        }
        // W tile: 32 x FOUT_PAD
        const int NF4 = FOUT_PAD / 4;
        for (int idx = tid; idx < 32 * NF4; idx += 256) {
            int r = idx / NF4, c4 = idx % NF4;
            int col = c4 * 4;
            float4 v = (col + 3 < FOUT_REAL)
                           ? *(const float4*)&W[(kt + r) * FOUT_REAL + col]
                           : make_float4(0.f, 0.f, 0.f, 0.f);
            *(float4*)&ws[r][col] = v;
        }
        __syncthreads();
#pragma unroll
        for (int kk = 0; kk < 32; kk++) {
            float xv[8];
#pragma unroll
            for (int i = 0; i < 8; i++) xv[i] = xs[nt * 8 + i][kk];
            float wv[TN];
            if (TN == 4) {
                float4 w4 = *(const float4*)&ws[kk][ft * 4];
                wv[0] = w4.x; wv[1] = w4.y; wv[2] = w4.z; wv[3] = w4.w;
            } else {
#pragma unroll
                for (int j = 0; j < TN; j += 2) {
                    float2 w2 = *(const float2*)&ws[kk][ft * TN + j];
                    wv[j] = w2.x; wv[j + 1] = w2.y;
                }
            }
#pragma unroll
            for (int i = 0; i < 8; i++)
#pragma unroll
                for (int j = 0; j < TN; j++)
                    acc[i][j] = fmaf(xv[i], wv[j], acc[i][j]);
        }
        __syncthreads();
    }
#pragma unroll
    for (int i = 0; i < 8; i++) {
        int n = n0 + nt * 8 + i;
        if (n < N_NODES) {
            if (TN == 4) {
                *(float4*)&g_h[n * FOUT_REAL + ft * 4] =
                    make_float4(acc[i][0], acc[i][1], acc[i][2], acc[i][3]);
            } else {
#pragma unroll
                for (int j = 0; j < TN; j++) {
                    int f = ft * TN + j;
                    if (f < FOUT_REAL) g_h[n * FOUT_REAL + f] = acc[i][j];
                }
            }
        }
    }
}

// ================= attention coefficients (warp per node) =================
__global__ void attn_coef128_kernel(const float* __restrict__ as,
                                    const float* __restrict__ ad) {
    int gtid = blockIdx.x * blockDim.x + threadIdx.x;
    int n = gtid >> 5;
    int lane = gtid & 31;
    if (n >= N_NODES) return;
    float4 v  = *(const float4*)&g_h[n * F12 + 4 * lane];
    float4 a4 = *(const float4*)&as[4 * lane];
    float4 d4 = *(const float4*)&ad[4 * lane];
    float ps = v.x * a4.x + v.y * a4.y + v.z * a4.z + v.w * a4.w;
    float pd = v.x * d4.x + v.y * d4.y + v.z * d4.z + v.w * d4.w;
    ps += __shfl_xor_sync(0xFFFFFFFFu, ps, 1);
    pd += __shfl_xor_sync(0xFFFFFFFFu, pd, 1);
    ps += __shfl_xor_sync(0xFFFFFFFFu, ps, 2);
    pd += __shfl_xor_sync(0xFFFFFFFFu, pd, 2);
    ps += __shfl_xor_sync(0xFFFFFFFFu, ps, 4);
    pd += __shfl_xor_sync(0xFFFFFFFFu, pd, 4);
    if ((lane & 7) == 0) {
        g_asrc[n * HEADS + (lane >> 3)] = ps;
        g_adst[n * HEADS + (lane >> 3)] = pd;
    }
}

__global__ void attn_coef188_kernel(const float* __restrict__ as,
                                    const float* __restrict__ ad) {
    int gtid = blockIdx.x * blockDim.x + threadIdx.x;
    int n = gtid >> 5;
    int lane = gtid & 31;
    if (n >= N_NODES) return;
    float hs[HEADS] = {0.f, 0.f, 0.f, 0.f};
    float hd[HEADS] = {0.f, 0.f, 0.f, 0.f};
#pragma unroll
    for (int k = 0; k < 6; k++) {
        int f = lane + 32 * k;
        if (f < F3) {
            float v = g_h[n * F3 + f];
            int hh = f / NCLS;
            hs[hh] = fmaf(v, as[f], hs[hh]);
            hd[hh] = fmaf(v, ad[f], hd[hh]);
        }
    }
#pragma unroll
    for (int h = 0; h < HEADS; h++) {
#pragma unroll
        for (int o = 16; o > 0; o >>= 1) {
            hs[h] += __shfl_xor_sync(0xFFFFFFFFu, hs[h], o);
            hd[h] += __shfl_xor_sync(0xFFFFFFFFu, hd[h], o);
        }
    }
    if (lane < HEADS) {
        g_asrc[n * HEADS + lane] = hs[lane];
        g_adst[n * HEADS + lane] = hd[lane];
    }
}

// ================= fused softmax + gather-aggregate (no-max) =================
// softmax is shift-invariant; alpha is bounded (|alpha| small), so exp(alpha)
// directly — removes the rescale dependency chain entirely.
// warp per dst node; lane owns feats [4*lane,4*lane+4), head hh = lane>>3.
__global__ void gat_agg128_kernel(const float* __restrict__ bias) {
    int gtid = blockIdx.x * blockDim.x + threadIdx.x;
    int n = gtid >> 5;
    int lane = gtid & 31;
    if (n >= N_NODES) return;
    int beg = g_rowptr[n];
    int deg = g_rowptr[n + 1] - beg;
    int hh = lane >> 3;
    const float4 adst4 = *(const float4*)&g_adst[n * HEADS];
    float adst_h = (hh == 0) ? adst4.x : (hh == 1) ? adst4.y : (hh == 2) ? adst4.z : adst4.w;

    float den = 0.f;
    float4 acc = make_float4(0.f, 0.f, 0.f, 0.f);
#pragma unroll 4
    for (int i = 0; i < deg; i++) {
        int src = g_col[beg + i];
        float4 s4 = *(const float4*)&g_asrc[src * HEADS];   // broadcast across warp
        float a = ((hh == 0) ? s4.x : (hh == 1) ? s4.y : (hh == 2) ? s4.z : s4.w) + adst_h;
        a = (a >= 0.f) ? a : NEG_SLOPE * a;
        float e = __expf(a);
        den += e;
        float4 v = *(const float4*)&g_h[src * F12 + 4 * lane];
        acc.x = fmaf(v.x, e, acc.x);
        acc.y = fmaf(v.y, e, acc.y);
        acc.z = fmaf(v.z, e, acc.z);
        acc.w = fmaf(v.w, e, acc.w);
    }
    float idv = 1.f / den;
    float4 b4 = *(const float4*)&bias[4 * lane];
    float4 o;
    o.x = fmaxf(fmaf(acc.x, idv, b4.x), 0.f);
    o.y = fmaxf(fmaf(acc.y, idv, b4.y), 0.f);
    o.z = fmaxf(fmaf(acc.z, idv, b4.z), 0.f);
    o.w = fmaxf(fmaf(acc.w, idv, b4.w), 0.f);
    *(float4*)&g_buf[n * F12 + 4 * lane] = o;
}

// layer 3 variant: lane owns feats lane+32k (k<6) spanning multiple heads.
__global__ void gat_agg188_kernel() {
    int gtid = blockIdx.x * blockDim.x + threadIdx.x;
    int n = gtid >> 5;
    int lane = gtid & 31;
    if (n >= N_NODES) return;
    int beg = g_rowptr[n];
    int deg = g_rowptr[n + 1] - beg;
    const float4 adst4 = *(const float4*)&g_adst[n * HEADS];

    int hhk[6];
#pragma unroll
    for (int k = 0; k < 6; k++) hhk[k] = (lane + 32 * k) / NCLS;

    float den[HEADS] = {0.f, 0.f, 0.f, 0.f};
    float acc[6] = {0.f, 0.f, 0.f, 0.f, 0.f, 0.f};

#pragma unroll 2
    for (int i = 0; i < deg; i++) {
        int src = g_col[beg + i];
        float4 s4 = *(const float4*)&g_asrc[src * HEADS];
        float e[HEADS];
        {
            float a0 = s4.x + adst4.x; a0 = (a0 >= 0.f) ? a0 : NEG_SLOPE * a0;
            float a1 = s4.y + adst4.y; a1 = (a1 >= 0.f) ? a1 : NEG_SLOPE * a1;
            float a2 = s4.z + adst4.z; a2 = (a2 >= 0.f) ? a2 : NEG_SLOPE * a2;
            float a3 = s4.w + adst4.w; a3 = (a3 >= 0.f) ? a3 : NEG_SLOPE * a3;
            e[0] = __expf(a0); e[1] = __expf(a1); e[2] = __expf(a2); e[3] = __expf(a3);
        }
#pragma unroll
        for (int h = 0; h < HEADS; h++) den[h] += e[h];
        const float* hrow = &g_h[src * F3];
#pragma unroll
        for (int k = 0; k < 6; k++) {
            int f = lane + 32 * k;
            if (f < F3) acc[k] = fmaf(hrow[f], e[hhk[k]], acc[k]);
        }
    }
#pragma unroll
    for (int k = 0; k < 6; k++) {
        int f = lane + 32 * k;
        if (f < F3) g_agg[n * F3 + f] = acc[k] / den[hhk[k]];
    }
}

// ================= finalize layer 3: head mean + bias + log_softmax =================
// tail: re-zero g_deg / g_flag / g_carry for the next call.
__global__ void finalize3_kernel(const float* __restrict__ b3, float* __restrict__ out) {
    int gtid = blockIdx.x * blockDim.x + threadIdx.x;
    if (gtid < N_NODES) g_deg[gtid] = 0;
    if (gtid < 64) { g_flag[gtid] = 0; g_carry[gtid] = 0; }
    int n = gtid >> 5;
    int lane = gtid & 31;
    if (n >= N_NODES) return;
    int c0 = lane, c1 = lane + 32;
    float v0 = -1e30f, v1 = -1e30f;
    const float* row = &g_agg[n * F3];
    if (c0 < NCLS)
        v0 = 0.25f * (row[c0] + row[NCLS + c0] + row[2 * NCLS + c0] + row[3 * NCLS + c0]) + b3[c0];
    if (c1 < NCLS)
        v1 = 0.25f * (row[c1] + row[NCLS + c1] + row[2 * NCLS + c1] + row[3 * NCLS + c1]) + b3[c1];
    float mm = fmaxf(v0, v1);
#pragma unroll
    for (int o = 16; o > 0; o >>= 1) mm = fmaxf(mm, __shfl_xor_sync(0xFFFFFFFFu, mm, o));
    float s = 0.f;
    if (c0 < NCLS) s += expf(v0 - mm);
    if (c1 < NCLS) s += expf(v1 - mm);
#pragma unroll
    for (int o = 16; o > 0; o >>= 1) s += __shfl_xor_sync(0xFFFFFFFFu, s, o);
    float lse = mm + logf(s);
    if (c0 < NCLS) out[n * NCLS + c0] = v0 - lse;
    if (c1 < NCLS) out[n * NCLS + c1] = v1 - lse;
}

// ================= launch =================
extern "C" void kernel_launch(void* const* d_in, const int* in_sizes, int n_in,
                              void* d_out, int out_size) {
    const float* x   = (const float*)d_in[0];
    const int*   ei  = (const int*)d_in[1];   // edge_index is int32 (JAX x64 disabled)
    const float* W1  = (const float*)d_in[2];
    const float* a1s = (const float*)d_in[3];
    const float* a1d = (const float*)d_in[4];
    const float* b1  = (const float*)d_in[5];
    const float* W2  = (const float*)d_in[6];
    const float* a2s = (const float*)d_in[7];
    const float* a2d = (const float*)d_in[8];
    const float* b2  = (const float*)d_in[9];
    const float* W3  = (const float*)d_in[10];
    const float* a3s = (const float*)d_in[11];
    const float* a3d = (const float*)d_in[12];
    const float* b3  = (const float*)d_in[13];
    float* out = (float*)d_out;

    float* g_buf_ptr = nullptr;
    cudaGetSymbolAddress((void**)&g_buf_ptr, g_buf);

    int eb = (ET + 255) / 256;
    int gemm_blocks = (N_NODES + 63) / 64;       // 782
    int wb = (N_NODES * 32 + 255) / 256;

    // CSR build
    csr_hist_kernel<<<eb, 256>>>(ei);                          // launch 0
    csr_scan_kernel<<<49, 1024>>>();                           // launch 1
    csr_scatter_kernel<<<eb, 256>>>(ei);                       // launch 2
    // layer 1
    gemm_tile_kernel<4, 128><<<gemm_blocks, 256>>>(x, W1);     // launch 3 (profiled)
    attn_coef128_kernel<<<wb, 256>>>(a1s, a1d);
    gat_agg128_kernel<<<wb, 256>>>(b1);
    // layer 2
    gemm_tile_kernel<4, 128><<<gemm_blocks, 256>>>(g_buf_ptr, W2);
    attn_coef128_kernel<<<wb, 256>>>(a2s, a2d);
    gat_agg128_kernel<<<wb, 256>>>(b2);
    // layer 3
    gemm_tile_kernel<6, 188><<<gemm_blocks, 256>>>(g_buf_ptr, W3);
    attn_coef188_kernel<<<wb, 256>>>(a3s, a3d);
    gat_agg188_kernel<<<wb, 256>>>();
    finalize3_kernel<<<wb, 256>>>(b3, out);
}